// round 1
// baseline (speedup 1.0000x reference)
#include <cuda_runtime.h>

#define NB 512
#define LL 2713
#define ZZ 58
#define GG 8
#define FFD 2048
#define NLY 6
#define RNAIN 1018
#define L1D 256
#define L2D 64
#define CATD 528

typedef unsigned long long u64;

// -------- scratch (device globals; no allocations allowed) --------
__device__ float g_r1[NB * L1D];
__device__ float g_r[NB * L2D];
__device__ float g_x[NB * ZZ * GG];
__device__ float g_chemt[LL * GG];        // chem_w transposed [l][g]
__device__ float g_ff2t[NLY * FFD * GG];  // ff2_w transposed  [layer][f][o]

// -------- packed f32x2 helpers (FFMA2 path ptxas won't emit from C++) ------
__device__ __forceinline__ u64 pk2(float lo, float hi) {
    u64 d; asm("mov.b64 %0,{%1,%2};" : "=l"(d) : "f"(lo), "f"(hi)); return d;
}
__device__ __forceinline__ void upk2(u64 d, float& lo, float& hi) {
    asm("mov.b64 {%0,%1},%2;" : "=f"(lo), "=f"(hi) : "l"(d));
}
__device__ __forceinline__ u64 ffma2(u64 a, u64 b, u64 c) {
    u64 d; asm("fma.rn.f32x2 %0,%1,%2,%3;" : "=l"(d) : "l"(a), "l"(b), "l"(c)); return d;
}
__device__ __forceinline__ u64 fadd2(u64 a, u64 b) {
    u64 d; asm("add.rn.f32x2 %0,%1,%2;" : "=l"(d) : "l"(a), "l"(b)); return d;
}

// -------- prep: transposes (run once per launch, cheap) --------
__global__ void prep_kernel(const float* __restrict__ chem_w,
                            const float* __restrict__ ff2_w) {
    int i = blockIdx.x * blockDim.x + threadIdx.x;
    if (i < LL * GG) {
        int l = i / GG, g = i % GG;
        g_chemt[i] = chem_w[g * LL + l];
    }
    int j = i - LL * GG;
    if (j >= 0 && j < NLY * FFD * GG) {
        int ly = j / (FFD * GG);
        int rem = j % (FFD * GG);
        int f = rem / GG, o = rem % GG;
        g_ff2t[j] = ff2_w[(ly * GG + o) * FFD + f];
    }
}

// -------- rna branch --------
__global__ void rna1_kernel(const float* __restrict__ rna,
                            const float* __restrict__ w,
                            const float* __restrict__ bias) {
    __shared__ float xs[8][RNAIN];
    int b0 = blockIdx.x * 8;
    for (int i = threadIdx.x; i < 8 * RNAIN; i += 256)
        (&xs[0][0])[i] = rna[b0 * RNAIN + i];
    __syncthreads();
    int j = threadIdx.x;  // 0..255 output feature
    float acc[8];
#pragma unroll
    for (int r = 0; r < 8; r++) acc[r] = 0.f;
    const float* wr = w + j * RNAIN;
    for (int k = 0; k < RNAIN; k++) {
        float wv = wr[k];
#pragma unroll
        for (int r = 0; r < 8; r++) acc[r] += xs[r][k] * wv;
    }
    float bv = bias[j];
#pragma unroll
    for (int r = 0; r < 8; r++) g_r1[(b0 + r) * L1D + j] = acc[r] + bv;
}

__global__ void rna2_kernel(const float* __restrict__ w,
                            const float* __restrict__ bias) {
    __shared__ float xs[8][L1D];
    int b0 = blockIdx.x * 8;
    for (int i = threadIdx.x; i < 8 * L1D; i += 64)
        (&xs[0][0])[i] = g_r1[b0 * L1D + i];
    __syncthreads();
    int j = threadIdx.x;  // 0..63
    float acc[8];
#pragma unroll
    for (int r = 0; r < 8; r++) acc[r] = 0.f;
    const float* wr = w + j * L1D;
    for (int k = 0; k < L1D; k++) {
        float wv = wr[k];
#pragma unroll
        for (int r = 0; r < 8; r++) acc[r] += xs[r][k] * wv;
    }
    float bv = bias[j];
#pragma unroll
    for (int r = 0; r < 8; r++) g_r[(b0 + r) * L2D + j] = acc[r] + bv;
}

// -------- embedding: x[b,z,g] = sum_l chem[g,l]*drug[b,l,z] + pos[g,z] ----
__global__ void embed_kernel(const float* __restrict__ drug,
                             const float* __restrict__ pos_w) {
    __shared__ float chem_s[256 * GG];
    __shared__ float red[8 * ZZ * GG];
    int b = blockIdx.x, tid = threadIdx.x;
    int z = tid % ZZ, lc = tid / ZZ;
    float acc[8];
#pragma unroll
    for (int g = 0; g < 8; g++) acc[g] = 0.f;
    const float* dbase = drug + (long)b * (LL * ZZ);
    for (int l0 = 0; l0 < LL; l0 += 256) {
        int cnt = min(256, LL - l0);
        __syncthreads();
        for (int i = tid; i < cnt * GG; i += 512) chem_s[i] = g_chemt[l0 * GG + i];
        __syncthreads();
        if (tid < 464) {
            for (int li = lc; li < cnt; li += 8) {
                float d = dbase[(l0 + li) * ZZ + z];
                const float* cs = chem_s + li * GG;
#pragma unroll
                for (int g = 0; g < 8; g++) acc[g] += cs[g] * d;
            }
        }
    }
    if (tid < 464) {
#pragma unroll
        for (int g = 0; g < 8; g++) red[(lc * ZZ + z) * GG + g] = acc[g];
    }
    __syncthreads();
    if (tid < 464) {
        int z2 = tid >> 3, g2 = tid & 7;
        float s = pos_w[g2 * ZZ + z2];
#pragma unroll
        for (int lc2 = 0; lc2 < 8; lc2++) s += red[(lc2 * ZZ + z2) * GG + g2];
        g_x[b * (ZZ * GG) + tid] = s;
    }
}

// -------- attention layer: qkv + softmax(HD=1) + out-proj + res + LN1 -----
__global__ void attn_kernel(const float* __restrict__ qkv_w,
                            const float* __restrict__ qkv_b,
                            const float* __restrict__ out_w,
                            const float* __restrict__ out_b,
                            const float* __restrict__ ln_g,
                            const float* __restrict__ ln_b, int layer) {
    qkv_w += layer * 24 * GG; qkv_b += layer * 24;
    out_w += layer * GG * GG; out_b += layer * GG;
    ln_g += layer * GG; ln_b += layer * GG;
    __shared__ float xs[ZZ * GG], qs[ZZ * GG], ks[ZZ * GG], vs[ZZ * GG], os_[ZZ * GG];
    __shared__ float wqkvT[GG * 24], bqkv[24], wout[GG * GG], bout[GG], lng[GG], lnb[GG];
    int b = blockIdx.x, tid = threadIdx.x;  // 256 threads
    if (tid < 192) { int j = tid / 8, kk = tid % 8; wqkvT[kk * 24 + j] = qkv_w[tid]; }
    if (tid < 24) bqkv[tid] = qkv_b[tid];
    if (tid < 64) wout[tid] = out_w[tid];
    if (tid < 8) { bout[tid] = out_b[tid]; lng[tid] = ln_g[tid]; lnb[tid] = ln_b[tid]; }
    for (int i = tid; i < ZZ * GG; i += 256) xs[i] = g_x[b * (ZZ * GG) + i];
    __syncthreads();
    // qkv projection: 58*24 outputs, each a dot-8
    for (int i = tid; i < ZZ * 24; i += 256) {
        int zz = i / 24, j = i % 24;
        float a = bqkv[j];
#pragma unroll
        for (int kk = 0; kk < 8; kk++) a += xs[zz * 8 + kk] * wqkvT[kk * 24 + j];
        if (j < 8) qs[zz * 8 + j] = a;
        else if (j < 16) ks[zz * 8 + (j - 8)] = a;
        else vs[zz * 8 + (j - 16)] = a;
    }
    __syncthreads();
    // per (s,h): softmax over t of q_s*k_t (scale = 1/sqrt(1) = 1)
    for (int i = tid; i < ZZ * GG; i += 256) {
        int h = i & 7;
        float qv = qs[i];
        float m = -1e30f;
        for (int t = 0; t < ZZ; t++) m = fmaxf(m, qv * ks[t * 8 + h]);
        float se = 0.f, av = 0.f;
        for (int t = 0; t < ZZ; t++) {
            float e = __expf(qv * ks[t * 8 + h] - m);
            se += e; av += e * vs[t * 8 + h];
        }
        os_[i] = av / se;
    }
    __syncthreads();
    // out-proj + residual + LayerNorm over G=8
    if (tid < ZZ) {
        float t8[8];
#pragma unroll
        for (int g = 0; g < 8; g++) {
            float a = bout[g];
#pragma unroll
            for (int kk = 0; kk < 8; kk++) a += os_[tid * 8 + kk] * wout[g * 8 + kk];
            t8[g] = a + xs[tid * 8 + g];
        }
        float mu = 0.f;
#pragma unroll
        for (int g = 0; g < 8; g++) mu += t8[g];
        mu *= 0.125f;
        float var = 0.f;
#pragma unroll
        for (int g = 0; g < 8; g++) { float d = t8[g] - mu; var += d * d; }
        var *= 0.125f;
        float inv = rsqrtf(var + 1e-5f);
#pragma unroll
        for (int g = 0; g < 8; g++)
            g_x[b * (ZZ * GG) + tid * 8 + g] = (t8[g] - mu) * inv * lng[g] + lnb[g];
    }
}

// -------- FFN layer (packed f32x2): warp owns 4 rows (2 row-pairs) --------
__global__ void ffn_kernel(const float* __restrict__ ff1_w,
                           const float* __restrict__ ff1_b,
                           const float* __restrict__ ff2_b,
                           const float* __restrict__ ln_g,
                           const float* __restrict__ ln_b, int layer) {
    ff1_w += layer * FFD * GG; ff1_b += layer * FFD;
    ff2_b += layer * GG; ln_g += layer * GG; ln_b += layer * GG;
    const float* ff2t = g_ff2t + layer * FFD * GG;
    int lane = threadIdx.x & 31, warp = threadIdx.x >> 5;
    int row0 = (blockIdx.x * 8 + warp) * 4;  // 29696 rows = 928 blocks * 32
    const float* xp = g_x + row0 * GG;
    u64 X2a[8], X2b[8], acc_a[8], acc_b[8];
#pragma unroll
    for (int kk = 0; kk < 8; kk++) {
        X2a[kk] = pk2(xp[kk], xp[8 + kk]);
        X2b[kk] = pk2(xp[16 + kk], xp[24 + kk]);
        acc_a[kk] = 0ull; acc_b[kk] = 0ull;
    }
    for (int j = lane; j < FFD; j += 32) {
        const float4* w1p = (const float4*)(ff1_w + j * 8);
        float4 wlo = w1p[0], whi = w1p[1];
        float b1 = ff1_b[j];
        float w1f[8] = {wlo.x, wlo.y, wlo.z, wlo.w, whi.x, whi.y, whi.z, whi.w};
        u64 ha = pk2(b1, b1), hb = ha;
#pragma unroll
        for (int kk = 0; kk < 8; kk++) {
            u64 ws = pk2(w1f[kk], w1f[kk]);
            ha = ffma2(X2a[kk], ws, ha);
            hb = ffma2(X2b[kk], ws, hb);
        }
        { float h0, h1; upk2(ha, h0, h1); ha = pk2(fmaxf(h0, 0.f), fmaxf(h1, 0.f)); }
        { float h0, h1; upk2(hb, h0, h1); hb = pk2(fmaxf(h0, 0.f), fmaxf(h1, 0.f)); }
        const float4* w2p = (const float4*)(ff2t + j * 8);
        float4 ulo = w2p[0], uhi = w2p[1];
        float w2f[8] = {ulo.x, ulo.y, ulo.z, ulo.w, uhi.x, uhi.y, uhi.z, uhi.w};
#pragma unroll
        for (int o = 0; o < 8; o++) {
            u64 ws = pk2(w2f[o], w2f[o]);
            acc_a[o] = ffma2(ha, ws, acc_a[o]);
            acc_b[o] = ffma2(hb, ws, acc_b[o]);
        }
    }
    // butterfly reduce (component-wise f32x2 adds)
#pragma unroll
    for (int o = 0; o < 8; o++) {
#pragma unroll
        for (int off = 16; off > 0; off >>= 1) {
            acc_a[o] = fadd2(acc_a[o], __shfl_xor_sync(0xffffffffu, acc_a[o], off));
            acc_b[o] = fadd2(acc_b[o], __shfl_xor_sync(0xffffffffu, acc_b[o], off));
        }
    }
    if (lane < 4) {
        float av[8];
#pragma unroll
        for (int o = 0; o < 8; o++) {
            float lo, hi, xlo, xhi;
            if (lane < 2) { upk2(acc_a[o], lo, hi); upk2(X2a[o], xlo, xhi); }
            else          { upk2(acc_b[o], lo, hi); upk2(X2b[o], xlo, xhi); }
            float s  = (lane & 1) ? hi : lo;
            float xv = (lane & 1) ? xhi : xlo;
            av[o] = s + ff2_b[o] + xv;
        }
        float mu = 0.f;
#pragma unroll
        for (int o = 0; o < 8; o++) mu += av[o];
        mu *= 0.125f;
        float var = 0.f;
#pragma unroll
        for (int o = 0; o < 8; o++) { float d = av[o] - mu; var += d * d; }
        var *= 0.125f;
        float inv = rsqrtf(var + 1e-5f);
#pragma unroll
        for (int o = 0; o < 8; o++)
            g_x[(row0 + lane) * GG + o] = (av[o] - mu) * inv * ln_g[o] + ln_b[o];
    }
}

// -------- head: concat [r, flat(x)] -> c1 -> c2 -> c3 --------
__global__ void head_kernel(const float* __restrict__ c1_w, const float* __restrict__ c1_b,
                            const float* __restrict__ c2_w, const float* __restrict__ c2_b,
                            const float* __restrict__ c3_w, const float* __restrict__ c3_b,
                            float* __restrict__ out) {
    __shared__ float cat[8][CATD];
    __shared__ float h1[8][L2D];
    __shared__ float h2[8][8];
    int b0 = blockIdx.x * 8, tid = threadIdx.x;  // 64 threads
    for (int i = tid; i < 8 * CATD; i += 64) {
        int r = i / CATD, c = i % CATD;
        cat[r][c] = (c < 64) ? g_r[(b0 + r) * L2D + c]
                             : g_x[(b0 + r) * (ZZ * GG) + (c - 64)];
    }
    __syncthreads();
    {
        int j = tid;
        float acc[8];
#pragma unroll
        for (int r = 0; r < 8; r++) acc[r] = 0.f;
        const float* wr = c1_w + j * CATD;
        for (int k = 0; k < CATD; k++) {
            float wv = wr[k];
#pragma unroll
            for (int r = 0; r < 8; r++) acc[r] += cat[r][k] * wv;
        }
        float bv = c1_b[j];
#pragma unroll
        for (int r = 0; r < 8; r++) h1[r][j] = acc[r] + bv;
    }
    __syncthreads();
    {
        int r = tid >> 3, o = tid & 7;
        float a = c2_b[o];
        for (int k = 0; k < 64; k++) a += h1[r][k] * c2_w[o * 64 + k];
        h2[r][o] = a;
    }
    __syncthreads();
    if (tid < 8) {
        float a = c3_b[0];
#pragma unroll
        for (int k = 0; k < 8; k++) a += h2[tid][k] * c3_w[k];
        out[b0 + tid] = a;
    }
}

extern "C" void kernel_launch(void* const* d_in, const int* in_sizes, int n_in,
                              void* d_out, int out_size) {
    const float* rna    = (const float*)d_in[0];
    const float* drug   = (const float*)d_in[1];
    const float* lin1_w = (const float*)d_in[2];
    const float* lin1_b = (const float*)d_in[3];
    const float* lin2_w = (const float*)d_in[4];
    const float* lin2_b = (const float*)d_in[5];
    const float* chem_w = (const float*)d_in[6];
    const float* pos_w  = (const float*)d_in[7];
    const float* qkv_w  = (const float*)d_in[8];
    const float* qkv_b  = (const float*)d_in[9];
    const float* out_w  = (const float*)d_in[10];
    const float* out_b  = (const float*)d_in[11];
    const float* ln1_g  = (const float*)d_in[12];
    const float* ln1_b  = (const float*)d_in[13];
    const float* ff1_w  = (const float*)d_in[14];
    const float* ff1_b  = (const float*)d_in[15];
    const float* ff2_w  = (const float*)d_in[16];
    const float* ff2_b  = (const float*)d_in[17];
    const float* ln2_g  = (const float*)d_in[18];
    const float* ln2_b  = (const float*)d_in[19];
    const float* c1_w   = (const float*)d_in[20];
    const float* c1_b   = (const float*)d_in[21];
    const float* c2_w   = (const float*)d_in[22];
    const float* c2_b   = (const float*)d_in[23];
    const float* c3_w   = (const float*)d_in[24];
    const float* c3_b   = (const float*)d_in[25];
    float* out = (float*)d_out;

    prep_kernel<<<(LL * GG + NLY * FFD * GG + 255) / 256, 256>>>(chem_w, ff2_w);
    rna1_kernel<<<64, 256>>>(rna, lin1_w, lin1_b);
    rna2_kernel<<<64, 64>>>(lin2_w, lin2_b);
    embed_kernel<<<NB, 512>>>(drug, pos_w);
    for (int i = 0; i < NLY; i++) {
        attn_kernel<<<NB, 256>>>(qkv_w, qkv_b, out_w, out_b, ln1_g, ln1_b, i);
        ffn_kernel<<<928, 256>>>(ff1_w, ff1_b, ff2_b, ln2_g, ln2_b, i);
    }
    head_kernel<<<64, 64>>>(c1_w, c1_b, c2_w, c2_b, c3_w, c3_b, out);
}

// round 2
// speedup vs baseline: 1.1219x; 1.1219x over previous
#include <cuda_runtime.h>

#define NB 512
#define LL 2713
#define ZZ 58
#define GG 8
#define FFD 2048
#define NLY 6
#define RNAIN 1018
#define L1D 256
#define L2D 64
#define CATD 528

typedef unsigned long long u64;

// -------- scratch (device globals; no allocations allowed) --------
__device__ float g_r1[NB * L1D];
__device__ float g_r[NB * L2D];
__device__ float g_x[NB * ZZ * GG];
__device__ float g_chemt[LL * GG];            // chem_w transposed [l][g]
__device__ float g_wpk[NLY * FFD * 20];       // [w1 x8 | w2t x8 | b1 | pad3] per j

// -------- packed f32x2 helpers (FFMA2 path ptxas won't emit from C++) ------
__device__ __forceinline__ u64 pk2(float lo, float hi) {
    u64 d; asm("mov.b64 %0,{%1,%2};" : "=l"(d) : "f"(lo), "f"(hi)); return d;
}
__device__ __forceinline__ void upk2(u64 d, float& lo, float& hi) {
    asm("mov.b64 {%0,%1},%2;" : "=f"(lo), "=f"(hi) : "l"(d));
}
__device__ __forceinline__ u64 ffma2(u64 a, u64 b, u64 c) {
    u64 d; asm("fma.rn.f32x2 %0,%1,%2,%3;" : "=l"(d) : "l"(a), "l"(b), "l"(c)); return d;
}
__device__ __forceinline__ u64 fadd2(u64 a, u64 b) {
    u64 d; asm("add.rn.f32x2 %0,%1,%2;" : "=l"(d) : "l"(a), "l"(b)); return d;
}

// -------- prep: transposes / weight packing (cheap, once per graph) --------
__global__ void prep_kernel(const float* __restrict__ chem_w,
                            const float* __restrict__ ff1_w,
                            const float* __restrict__ ff1_b,
                            const float* __restrict__ ff2_w) {
    int i = blockIdx.x * blockDim.x + threadIdx.x;
    if (i < LL * GG) {
        int l = i / GG, g = i % GG;
        g_chemt[i] = chem_w[g * LL + l];
    }
    int n = i - LL * GG;
    if (n >= 0 && n < NLY * FFD * 20) {
        int ly = n / (FFD * 20);
        int rem = n % (FFD * 20);
        int j = rem / 20, s = rem % 20;
        float v = 0.f;
        if (s < 8)       v = ff1_w[(ly * FFD + j) * GG + s];
        else if (s < 16) v = ff2_w[(ly * GG + (s - 8)) * FFD + j];
        else if (s == 16) v = ff1_b[ly * FFD + j];
        g_wpk[n] = v;
    }
}

// -------- rna branch --------
__global__ void rna1_kernel(const float* __restrict__ rna,
                            const float* __restrict__ w,
                            const float* __restrict__ bias) {
    __shared__ float xs[8][RNAIN];
    int b0 = blockIdx.x * 8;
    for (int i = threadIdx.x; i < 8 * RNAIN; i += 256)
        (&xs[0][0])[i] = rna[b0 * RNAIN + i];
    __syncthreads();
    int j = threadIdx.x;
    float acc[8];
#pragma unroll
    for (int r = 0; r < 8; r++) acc[r] = 0.f;
    const float* wr = w + j * RNAIN;
#pragma unroll 2
    for (int k = 0; k < RNAIN; k++) {
        float wv = wr[k];
#pragma unroll
        for (int r = 0; r < 8; r++) acc[r] += xs[r][k] * wv;
    }
    float bv = bias[j];
#pragma unroll
    for (int r = 0; r < 8; r++) g_r1[(b0 + r) * L1D + j] = acc[r] + bv;
}

__global__ void rna2_kernel(const float* __restrict__ w,
                            const float* __restrict__ bias) {
    __shared__ float xs[8][L1D];
    int b0 = blockIdx.x * 8;
    for (int i = threadIdx.x; i < 8 * L1D; i += 64)
        (&xs[0][0])[i] = g_r1[b0 * L1D + i];
    __syncthreads();
    int j = threadIdx.x;
    float acc[8];
#pragma unroll
    for (int r = 0; r < 8; r++) acc[r] = 0.f;
    const float* wr = w + j * L1D;
#pragma unroll 4
    for (int k = 0; k < L1D; k++) {
        float wv = wr[k];
#pragma unroll
        for (int r = 0; r < 8; r++) acc[r] += xs[r][k] * wv;
    }
    float bv = bias[j];
#pragma unroll
    for (int r = 0; r < 8; r++) g_r[(b0 + r) * L2D + j] = acc[r] + bv;
}

// -------- embedding: x[b,z,g] = sum_l chem[g,l]*drug[b,l,z] + pos[g,z] ----
// 512 threads = 16 warps/block; warp owns rows l = warp, warp+16, ...
// lane owns z-pair (2*lane, 2*lane+1); g packed into f32x2 pairs.
__global__ __launch_bounds__(512) void embed_kernel(const float* __restrict__ drug,
                                                    const float* __restrict__ pos_w) {
    __shared__ float red[8][ZZ * GG];
    int b = blockIdx.x, tid = threadIdx.x;
    int warp = tid >> 5, lane = tid & 31;
    const float* dbase = drug + (long)b * (LL * ZZ);
    bool act = lane < 29;
    int zoff = 2 * lane;
    u64 acc[2][4];
#pragma unroll
    for (int zi = 0; zi < 2; zi++)
#pragma unroll
        for (int gp = 0; gp < 4; gp++) acc[zi][gp] = 0ull;

#pragma unroll 4
    for (int l = warp; l < LL; l += 16) {
        float2 d = act ? *(const float2*)(dbase + l * ZZ + zoff) : make_float2(0.f, 0.f);
        const ulonglong2* crow = (const ulonglong2*)(g_chemt + l * GG);
        ulonglong2 cA = crow[0], cB = crow[1];
        u64 d0 = pk2(d.x, d.x), d1 = pk2(d.y, d.y);
        acc[0][0] = ffma2(cA.x, d0, acc[0][0]);
        acc[0][1] = ffma2(cA.y, d0, acc[0][1]);
        acc[0][2] = ffma2(cB.x, d0, acc[0][2]);
        acc[0][3] = ffma2(cB.y, d0, acc[0][3]);
        acc[1][0] = ffma2(cA.x, d1, acc[1][0]);
        acc[1][1] = ffma2(cA.y, d1, acc[1][1]);
        acc[1][2] = ffma2(cB.x, d1, acc[1][2]);
        acc[1][3] = ffma2(cB.y, d1, acc[1][3]);
    }
    // two-stage cross-warp reduction (16 warps -> 8 -> scalar)
    if (warp >= 8 && act) {
#pragma unroll
        for (int zi = 0; zi < 2; zi++)
#pragma unroll
            for (int gp = 0; gp < 4; gp++)
                *(u64*)&red[warp - 8][(zoff + zi) * GG + 2 * gp] = acc[zi][gp];
    }
    __syncthreads();
    if (warp < 8 && act) {
#pragma unroll
        for (int zi = 0; zi < 2; zi++)
#pragma unroll
            for (int gp = 0; gp < 4; gp++)
                acc[zi][gp] = fadd2(acc[zi][gp], *(u64*)&red[warp][(zoff + zi) * GG + 2 * gp]);
    }
    __syncthreads();
    if (warp < 8 && act) {
#pragma unroll
        for (int zi = 0; zi < 2; zi++)
#pragma unroll
            for (int gp = 0; gp < 4; gp++)
                *(u64*)&red[warp][(zoff + zi) * GG + 2 * gp] = acc[zi][gp];
    }
    __syncthreads();
    if (tid < ZZ * GG) {
        int z = tid >> 3, g = tid & 7;
        float s = pos_w[g * ZZ + z];
#pragma unroll
        for (int w = 0; w < 8; w++) s += red[w][tid];
        g_x[b * (ZZ * GG) + tid] = s;
    }
}

// -------- attention layer: qkv + softmax(HD=1) + out-proj + res + LN1 -----
__global__ __launch_bounds__(256) void attn_kernel(const float* __restrict__ qkv_w,
                            const float* __restrict__ qkv_b,
                            const float* __restrict__ out_w,
                            const float* __restrict__ out_b,
                            const float* __restrict__ ln_g,
                            const float* __restrict__ ln_b, int layer) {
    qkv_w += layer * 24 * GG; qkv_b += layer * 24;
    out_w += layer * GG * GG; out_b += layer * GG;
    ln_g += layer * GG; ln_b += layer * GG;
    __shared__ float xs[ZZ * GG], qs[ZZ * GG], os_[ZZ * GG];
    __shared__ float2 kv[ZZ * GG];
    __shared__ float wqkvT[GG * 24], bqkv[24], wout[GG * GG], bout[GG], lng[GG], lnb[GG];
    __shared__ float kmax[GG], kmin[GG];
    int b = blockIdx.x, tid = threadIdx.x;
    if (tid < 192) { int j = tid / 8, kk = tid % 8; wqkvT[kk * 24 + j] = qkv_w[tid]; }
    if (tid < 24) bqkv[tid] = qkv_b[tid];
    if (tid < 64) wout[tid] = out_w[tid];
    if (tid < 8) { bout[tid] = out_b[tid]; lng[tid] = ln_g[tid]; lnb[tid] = ln_b[tid]; }
    for (int i = tid; i < ZZ * GG; i += 256) xs[i] = g_x[b * (ZZ * GG) + i];
    __syncthreads();
    // qkv projection: 58*24 outputs, each a dot-8
    for (int i = tid; i < ZZ * 24; i += 256) {
        int zz = i / 24, j = i % 24;
        float a = bqkv[j];
#pragma unroll
        for (int kk = 0; kk < 8; kk++) a += xs[zz * 8 + kk] * wqkvT[kk * 24 + j];
        if (j < 8) qs[zz * 8 + j] = a;
        else if (j < 16) kv[zz * 8 + (j - 8)].x = a;
        else kv[zz * 8 + (j - 16)].y = a;
    }
    __syncthreads();
    if (tid < 8) {
        float mx = -1e30f, mn = 1e30f;
        for (int t = 0; t < ZZ; t++) {
            float k = kv[t * 8 + tid].x;
            mx = fmaxf(mx, k); mn = fminf(mn, k);
        }
        kmax[tid] = mx; kmin[tid] = mn;
    }
    __syncthreads();
    // per (s,h): softmax over t of q_s*k_t  (HD=1 => max via kmax/kmin)
    for (int i = tid; i < ZZ * GG; i += 256) {
        int h = i & 7;
        float qv = qs[i];
        float m = (qv >= 0.f) ? qv * kmax[h] : qv * kmin[h];
        float se = 0.f, av = 0.f;
#pragma unroll 2
        for (int t = 0; t < ZZ; t++) {
            float2 kvv = kv[t * 8 + h];
            float e = __expf(qv * kvv.x - m);
            se += e; av += e * kvv.y;
        }
        os_[i] = av / se;
    }
    __syncthreads();
    // out-proj + residual + LayerNorm over G=8
    if (tid < ZZ) {
        float t8[8];
#pragma unroll
        for (int g = 0; g < 8; g++) {
            float a = bout[g];
#pragma unroll
            for (int kk = 0; kk < 8; kk++) a += os_[tid * 8 + kk] * wout[g * 8 + kk];
            t8[g] = a + xs[tid * 8 + g];
        }
        float mu = 0.f;
#pragma unroll
        for (int g = 0; g < 8; g++) mu += t8[g];
        mu *= 0.125f;
        float var = 0.f;
#pragma unroll
        for (int g = 0; g < 8; g++) { float d = t8[g] - mu; var += d * d; }
        var *= 0.125f;
        float inv = rsqrtf(var + 1e-5f);
#pragma unroll
        for (int g = 0; g < 8; g++)
            g_x[b * (ZZ * GG) + tid * 8 + g] = (t8[g] - mu) * inv * lng[g] + lnb[g];
    }
}

// -------- FFN layer (packed f32x2): warp owns 4 rows (2 row-pairs) --------
__global__ __launch_bounds__(256) void ffn_kernel(const float* __restrict__ ff2_b,
                           const float* __restrict__ ln_g,
                           const float* __restrict__ ln_b, int layer) {
    const float* wpk = g_wpk + layer * FFD * 20;
    ff2_b += layer * GG; ln_g += layer * GG; ln_b += layer * GG;
    int lane = threadIdx.x & 31, warp = threadIdx.x >> 5;
    int row0 = (blockIdx.x * 8 + warp) * 4;   // 29696 rows = 928 blocks * 32
    const float* xp = g_x + row0 * GG;
    u64 X2a[8], X2b[8], acc_a[8], acc_b[8];
#pragma unroll
    for (int kk = 0; kk < 8; kk++) {
        X2a[kk] = pk2(xp[kk], xp[8 + kk]);
        X2b[kk] = pk2(xp[16 + kk], xp[24 + kk]);
        acc_a[kk] = 0ull; acc_b[kk] = 0ull;
    }
#pragma unroll 4
    for (int it = 0; it < FFD / 32; it++) {
        const float4* wp = (const float4*)(wpk + (long)(it * 32 + lane) * 20);
        float4 a0 = wp[0], a1 = wp[1], a2 = wp[2], a3 = wp[3];
        float b1 = ((const float*)wp)[16];
        float w1f[8] = {a0.x, a0.y, a0.z, a0.w, a1.x, a1.y, a1.z, a1.w};
        float w2f[8] = {a2.x, a2.y, a2.z, a2.w, a3.x, a3.y, a3.z, a3.w};
        u64 ha = pk2(b1, b1), hb = ha;
#pragma unroll
        for (int kk = 0; kk < 8; kk++) {
            u64 ws = pk2(w1f[kk], w1f[kk]);
            ha = ffma2(X2a[kk], ws, ha);
            hb = ffma2(X2b[kk], ws, hb);
        }
        { float h0, h1; upk2(ha, h0, h1); ha = pk2(fmaxf(h0, 0.f), fmaxf(h1, 0.f)); }
        { float h0, h1; upk2(hb, h0, h1); hb = pk2(fmaxf(h0, 0.f), fmaxf(h1, 0.f)); }
#pragma unroll
        for (int o = 0; o < 8; o++) {
            u64 ws = pk2(w2f[o], w2f[o]);
            acc_a[o] = ffma2(ha, ws, acc_a[o]);
            acc_b[o] = ffma2(hb, ws, acc_b[o]);
        }
    }
    // butterfly reduce (component-wise f32x2 adds)
#pragma unroll
    for (int o = 0; o < 8; o++) {
#pragma unroll
        for (int off = 16; off > 0; off >>= 1) {
            acc_a[o] = fadd2(acc_a[o], __shfl_xor_sync(0xffffffffu, acc_a[o], off));
            acc_b[o] = fadd2(acc_b[o], __shfl_xor_sync(0xffffffffu, acc_b[o], off));
        }
    }
    if (lane < 4) {
        float av[8];
#pragma unroll
        for (int o = 0; o < 8; o++) {
            float lo, hi, xlo, xhi;
            if (lane < 2) { upk2(acc_a[o], lo, hi); upk2(X2a[o], xlo, xhi); }
            else          { upk2(acc_b[o], lo, hi); upk2(X2b[o], xlo, xhi); }
            float s  = (lane & 1) ? hi : lo;
            float xv = (lane & 1) ? xhi : xlo;
            av[o] = s + ff2_b[o] + xv;
        }
        float mu = 0.f;
#pragma unroll
        for (int o = 0; o < 8; o++) mu += av[o];
        mu *= 0.125f;
        float var = 0.f;
#pragma unroll
        for (int o = 0; o < 8; o++) { float d = av[o] - mu; var += d * d; }
        var *= 0.125f;
        float inv = rsqrtf(var + 1e-5f);
#pragma unroll
        for (int o = 0; o < 8; o++)
            g_x[(row0 + lane) * GG + o] = (av[o] - mu) * inv * ln_g[o] + ln_b[o];
    }
}

// -------- head: concat [r, flat(x)] -> c1 -> c2 -> c3 --------
__global__ void head_kernel(const float* __restrict__ c1_w, const float* __restrict__ c1_b,
                            const float* __restrict__ c2_w, const float* __restrict__ c2_b,
                            const float* __restrict__ c3_w, const float* __restrict__ c3_b,
                            float* __restrict__ out) {
    __shared__ float cat[8][CATD];
    __shared__ float h1[8][L2D];
    __shared__ float h2[8][8];
    int b0 = blockIdx.x * 8, tid = threadIdx.x;  // 64 threads
    for (int i = tid; i < 8 * CATD; i += 64) {
        int r = i / CATD, c = i % CATD;
        cat[r][c] = (c < 64) ? g_r[(b0 + r) * L2D + c]
                             : g_x[(b0 + r) * (ZZ * GG) + (c - 64)];
    }
    __syncthreads();
    {
        int j = tid;
        float acc[8];
#pragma unroll
        for (int r = 0; r < 8; r++) acc[r] = 0.f;
        const float* wr = c1_w + j * CATD;
#pragma unroll 4
        for (int k = 0; k < CATD; k++) {
            float wv = wr[k];
#pragma unroll
            for (int r = 0; r < 8; r++) acc[r] += cat[r][k] * wv;
        }
        float bv = c1_b[j];
#pragma unroll
        for (int r = 0; r < 8; r++) h1[r][j] = acc[r] + bv;
    }
    __syncthreads();
    {
        int r = tid >> 3, o = tid & 7;
        float a = c2_b[o];
#pragma unroll 4
        for (int k = 0; k < 64; k++) a += h1[r][k] * c2_w[o * 64 + k];
        h2[r][o] = a;
    }
    __syncthreads();
    if (tid < 8) {
        float a = c3_b[0];
#pragma unroll
        for (int k = 0; k < 8; k++) a += h2[tid][k] * c3_w[k];
        out[b0 + tid] = a;
    }
}

extern "C" void kernel_launch(void* const* d_in, const int* in_sizes, int n_in,
                              void* d_out, int out_size) {
    const float* rna    = (const float*)d_in[0];
    const float* drug   = (const float*)d_in[1];
    const float* lin1_w = (const float*)d_in[2];
    const float* lin1_b = (const float*)d_in[3];
    const float* lin2_w = (const float*)d_in[4];
    const float* lin2_b = (const float*)d_in[5];
    const float* chem_w = (const float*)d_in[6];
    const float* pos_w  = (const float*)d_in[7];
    const float* qkv_w  = (const float*)d_in[8];
    const float* qkv_b  = (const float*)d_in[9];
    const float* out_w  = (const float*)d_in[10];
    const float* out_b  = (const float*)d_in[11];
    const float* ln1_g  = (const float*)d_in[12];
    const float* ln1_b  = (const float*)d_in[13];
    const float* ff1_w  = (const float*)d_in[14];
    const float* ff1_b  = (const float*)d_in[15];
    const float* ff2_w  = (const float*)d_in[16];
    const float* ff2_b  = (const float*)d_in[17];
    const float* ln2_g  = (const float*)d_in[18];
    const float* ln2_b  = (const float*)d_in[19];
    const float* c1_w   = (const float*)d_in[20];
    const float* c1_b   = (const float*)d_in[21];
    const float* c2_w   = (const float*)d_in[22];
    const float* c2_b   = (const float*)d_in[23];
    const float* c3_w   = (const float*)d_in[24];
    const float* c3_b   = (const float*)d_in[25];
    float* out = (float*)d_out;

    prep_kernel<<<(LL * GG + NLY * FFD * 20 + 255) / 256, 256>>>(chem_w, ff1_w, ff1_b, ff2_w);
    rna1_kernel<<<64, 256>>>(rna, lin1_w, lin1_b);
    rna2_kernel<<<64, 64>>>(lin2_w, lin2_b);
    embed_kernel<<<NB, 512>>>(drug, pos_w);
    for (int i = 0; i < NLY; i++) {
        attn_kernel<<<NB, 256>>>(qkv_w, qkv_b, out_w, out_b, ln1_g, ln1_b, i);
        ffn_kernel<<<928, 256>>>(ff2_b, ln2_g, ln2_b, i);
    }
    head_kernel<<<64, 64>>>(c1_w, c1_b, c2_w, c2_b, c3_w, c3_b, out);
}